// round 1
// baseline (speedup 1.0000x reference)
#include <cuda_runtime.h>
#include <cstdint>

#define T_TABLES 4
#define B_BATCH  8192
#define L_LEN    50
#define D_DIM    128
#define VOCAB_N  100000

#define ROWS_PER_BLOCK 64
#define MAIN_THREADS   256
#define POOL_STRIDE    132   // 128 + 4 pad -> rows land 16 banks apart

// Scratch (device globals: allocation-free rule)
__device__ float g_W12[D_DIM * D_DIM];
__device__ float g_Wc[D_DIM * D_DIM];
__device__ float g_bc[D_DIM];

// ---------------------------------------------------------------------------
// W12[i][j] = sum_k W1[k][i] * W2[j][k]      (= (W1^T W2^T)[i][j])
// ---------------------------------------------------------------------------
__global__ void mm1_kernel(const float* __restrict__ W1,
                           const float* __restrict__ W2) {
    __shared__ float colA[D_DIM];
    int i = blockIdx.x, j = threadIdx.x;
    colA[j] = W1[j * D_DIM + i];
    __syncthreads();
    float s = 0.f;
#pragma unroll 8
    for (int k = 0; k < D_DIM; ++k) s += colA[k] * W2[j * D_DIM + k];
    g_W12[i * D_DIM + j] = s;
}

// ---------------------------------------------------------------------------
// Wc[i][j] = sum_k W12[i][k] * W3[j][k]      (= W12 W3^T)
// ---------------------------------------------------------------------------
__global__ void mm2_kernel(const float* __restrict__ W3) {
    __shared__ float rowA[D_DIM];
    int i = blockIdx.x, j = threadIdx.x;
    rowA[j] = g_W12[i * D_DIM + j];
    __syncthreads();
    float s = 0.f;
#pragma unroll 8
    for (int k = 0; k < D_DIM; ++k) s += rowA[k] * W3[j * D_DIM + k];
    g_Wc[i * D_DIM + j] = s;
}

// ---------------------------------------------------------------------------
// bc[j] = sum_k (b1·W2^T + b2)[k] * W3[j][k] + b3[j]
// ---------------------------------------------------------------------------
__global__ void bias_kernel(const float* __restrict__ b1,
                            const float* __restrict__ W2,
                            const float* __restrict__ b2,
                            const float* __restrict__ W3,
                            const float* __restrict__ b3) {
    __shared__ float b12[D_DIM];
    int j = threadIdx.x;
    float s = b2[j];
#pragma unroll 8
    for (int k = 0; k < D_DIM; ++k) s += b1[k] * W2[j * D_DIM + k];
    b12[j] = s;
    __syncthreads();
    float s2 = b3[j];
#pragma unroll 8
    for (int k = 0; k < D_DIM; ++k) s2 += b12[k] * W3[j * D_DIM + k];
    g_bc[j] = s2;
}

// ---------------------------------------------------------------------------
// Fused: jagged gather + sum pool + (pooled @ Wc + bc)
// grid = (T*B)/64 = 512 blocks, 256 threads
// ---------------------------------------------------------------------------
__global__ __launch_bounds__(MAIN_THREADS, 2)
void fused_kernel(const int* __restrict__ indices,
                  const int* __restrict__ lengths,
                  const float* __restrict__ tables,
                  float* __restrict__ out) {
    extern __shared__ float sm[];
    float* Wc_sh  = sm;                       // 16384 floats
    float* bc_sh  = sm + D_DIM * D_DIM;       // 128
    float* pooled = bc_sh + D_DIM;            // 64 * 132

    const int tid = threadIdx.x;

    // Stage Wc + bc into shared (vectorized; overlaps with gather issue below)
    {
        const float4* src = (const float4*)g_Wc;
        float4* dst = (float4*)Wc_sh;
#pragma unroll
        for (int i = tid; i < (D_DIM * D_DIM) / 4; i += MAIN_THREADS) dst[i] = src[i];
        if (tid < D_DIM) bc_sh[tid] = g_bc[tid];
    }

    // ---- Phase A: gather + pool. warp w handles 8 rows; lane owns one float4 ----
    const int warp = tid >> 5, lane = tid & 31;
    const int base = blockIdx.x * ROWS_PER_BLOCK;

#pragma unroll 1
    for (int rr = 0; rr < 8; ++rr) {
        const int rl = warp * 8 + rr;          // local row 0..63
        const int g  = base + rl;              // global row = t*B + b
        const int t  = g >> 13;                // B = 8192
        const int len = lengths[g];
        const int* idxp = indices + (size_t)g * L_LEN;
        const float4* tab =
            (const float4*)tables + (size_t)t * ((size_t)VOCAB_N * (D_DIM / 4));

        float4 a0 = make_float4(0.f, 0.f, 0.f, 0.f);
        float4 a1 = make_float4(0.f, 0.f, 0.f, 0.f);
        int l = 0;
        for (; l + 1 < len; l += 2) {
            const int i0 = idxp[l];
            const int i1 = idxp[l + 1];
            const float4 v0 = tab[(size_t)i0 * (D_DIM / 4) + lane];
            const float4 v1 = tab[(size_t)i1 * (D_DIM / 4) + lane];
            a0.x += v0.x; a0.y += v0.y; a0.z += v0.z; a0.w += v0.w;
            a1.x += v1.x; a1.y += v1.y; a1.z += v1.z; a1.w += v1.w;
        }
        if (l < len) {
            const int i0 = idxp[l];
            const float4 v0 = tab[(size_t)i0 * (D_DIM / 4) + lane];
            a0.x += v0.x; a0.y += v0.y; a0.z += v0.z; a0.w += v0.w;
        }
        a0.x += a1.x; a0.y += a1.y; a0.z += a1.z; a0.w += a1.w;
        *(float4*)&pooled[rl * POOL_STRIDE + lane * 4] = a0;
    }
    __syncthreads();

    // ---- Phase B: out[64,128] = pooled @ Wc + bc. 4x8 register tile/thread ----
    const int tx = tid & 15;        // 16 col groups of 8
    const int ty = tid >> 4;        // 16 row groups of 4
    const int r0 = ty * 4;
    const int c0 = tx * 8;

    float acc[4][8];
#pragma unroll
    for (int i = 0; i < 4; ++i)
#pragma unroll
        for (int j = 0; j < 8; ++j) acc[i][j] = bc_sh[c0 + j];

#pragma unroll 2
    for (int d = 0; d < D_DIM; ++d) {
        const float a0_ = pooled[(r0 + 0) * POOL_STRIDE + d];
        const float a1_ = pooled[(r0 + 1) * POOL_STRIDE + d];
        const float a2_ = pooled[(r0 + 2) * POOL_STRIDE + d];
        const float a3_ = pooled[(r0 + 3) * POOL_STRIDE + d];
        const float4 w0 = *(const float4*)&Wc_sh[d * D_DIM + c0];
        const float4 w1 = *(const float4*)&Wc_sh[d * D_DIM + c0 + 4];
        const float w[8] = {w0.x, w0.y, w0.z, w0.w, w1.x, w1.y, w1.z, w1.w};
#pragma unroll
        for (int j = 0; j < 8; ++j) {
            acc[0][j] += a0_ * w[j];
            acc[1][j] += a1_ * w[j];
            acc[2][j] += a2_ * w[j];
            acc[3][j] += a3_ * w[j];
        }
    }

#pragma unroll
    for (int i = 0; i < 4; ++i) {
        float* orow = out + (size_t)(base + r0 + i) * D_DIM + c0;
        float4 o0 = make_float4(acc[i][0], acc[i][1], acc[i][2], acc[i][3]);
        float4 o1 = make_float4(acc[i][4], acc[i][5], acc[i][6], acc[i][7]);
        *(float4*)orow = o0;
        *(float4*)(orow + 4) = o1;
    }
}

// ---------------------------------------------------------------------------
extern "C" void kernel_launch(void* const* d_in, const int* in_sizes, int n_in,
                              void* d_out, int out_size) {
    const int*   indices = (const int*)d_in[0];
    const int*   lengths = (const int*)d_in[1];
    const float* tables  = (const float*)d_in[2];
    const float* W1      = (const float*)d_in[3];
    const float* b1      = (const float*)d_in[4];
    const float* W2      = (const float*)d_in[5];
    const float* b2      = (const float*)d_in[6];
    const float* W3      = (const float*)d_in[7];
    const float* b3      = (const float*)d_in[8];
    float* out = (float*)d_out;

    mm1_kernel<<<D_DIM, D_DIM>>>(W1, W2);
    mm2_kernel<<<D_DIM, D_DIM>>>(W3);
    bias_kernel<<<1, D_DIM>>>(b1, W2, b2, W3, b3);

    const int smem_bytes =
        (D_DIM * D_DIM + D_DIM + ROWS_PER_BLOCK * POOL_STRIDE) * (int)sizeof(float);
    cudaFuncSetAttribute(fused_kernel,
                         cudaFuncAttributeMaxDynamicSharedMemorySize, smem_bytes);

    const int grid = (T_TABLES * B_BATCH) / ROWS_PER_BLOCK;  // 512
    fused_kernel<<<grid, MAIN_THREADS, smem_bytes>>>(indices, lengths, tables, out);
}

// round 2
// speedup vs baseline: 1.5597x; 1.5597x over previous
#include <cuda_runtime.h>
#include <cstdint>

#define T_TABLES 4
#define B_BATCH  8192
#define L_LEN    50
#define D_DIM    128
#define VOCAB_N  100000
#define ROWS_TOTAL (T_TABLES * B_BATCH)   // 32768

// Scratch (device globals: allocation-free rule)
__device__ float g_Wc[D_DIM * D_DIM];
__device__ float g_bc[D_DIM];
__device__ float g_pooled[(size_t)ROWS_TOTAL * D_DIM];   // 16.7 MB

// ---------------------------------------------------------------------------
// Kernel 1: jagged gather + sum pool (1 warp per output row), and blocks
// 0..127 additionally collapse the 3 linears: Wc = W1^T W2^T W3^T,
// bc = (b1 W2^T + b2) W3^T + b3. Runs concurrently with the gather work.
// ---------------------------------------------------------------------------
__global__ __launch_bounds__(256)
void gather_kernel(const int* __restrict__ indices,
                   const int* __restrict__ lengths,
                   const float* __restrict__ tables,
                   const float* __restrict__ W1, const float* __restrict__ b1,
                   const float* __restrict__ W2, const float* __restrict__ b2,
                   const float* __restrict__ W3, const float* __restrict__ b3) {
    __shared__ float s_col[D_DIM];
    __shared__ float s_tmp[D_DIM];
    __shared__ float s_b12[D_DIM];

    const int tid = threadIdx.x;

    // ---- weight/bias precompute (blocks 0..127 only; block-uniform syncs) ----
    if (blockIdx.x < D_DIM) {
        const int i = blockIdx.x;
        const int j = tid;
        if (tid < D_DIM) s_col[tid] = W1[tid * D_DIM + i];   // W1 column i
        __syncthreads();
        if (tid < D_DIM) {
            float s = 0.f;
#pragma unroll 8
            for (int k = 0; k < D_DIM; ++k) s += s_col[k] * W2[j * D_DIM + k];
            s_tmp[j] = s;                                    // W12[i][j]
        }
        __syncthreads();
        if (tid < D_DIM) {
            float s = 0.f;
#pragma unroll 8
            for (int m = 0; m < D_DIM; ++m) s += s_tmp[m] * W3[j * D_DIM + m];
            g_Wc[i * D_DIM + j] = s;                         // Wc[i][j]
        }
        if (i == 0) {
            if (tid < D_DIM) {
                float s = b2[j];
#pragma unroll 8
                for (int k = 0; k < D_DIM; ++k) s += b1[k] * W2[j * D_DIM + k];
                s_b12[j] = s;
            }
            __syncthreads();
            if (tid < D_DIM) {
                float s = b3[j];
#pragma unroll 8
                for (int m = 0; m < D_DIM; ++m) s += s_b12[m] * W3[j * D_DIM + m];
                g_bc[j] = s;
            }
        }
    }

    // ---- gather + pool: this warp owns row g; lane owns one float4 of D ----
    const int g    = (int)((blockIdx.x * 256u + tid) >> 5);   // 0..32767
    const int lane = tid & 31;
    const int t    = g >> 13;                                  // B = 8192
    const int len  = lengths[g];
    const int* idxp = indices + (size_t)g * L_LEN;

    // hold all 50 indices in 2 regs per lane; broadcast via shfl
    const int i_lo = idxp[lane];
    const int i_hi = (lane < (L_LEN - 32)) ? idxp[32 + lane] : 0;

    const float4* tab =
        (const float4*)tables + (size_t)t * ((size_t)VOCAB_N * (D_DIM / 4));

    float4 a0 = make_float4(0.f, 0.f, 0.f, 0.f);
    float4 a1 = a0, a2 = a0, a3 = a0;

    auto getidx = [&](int p) -> int {
        return (p < 32) ? __shfl_sync(0xffffffffu, i_lo, p)
                        : __shfl_sync(0xffffffffu, i_hi, p - 32);
    };

    int l = 0;
    for (; l + 3 < len; l += 4) {
        const int j0 = getidx(l + 0);
        const int j1 = getidx(l + 1);
        const int j2 = getidx(l + 2);
        const int j3 = getidx(l + 3);
        const float4 v0 = __ldg(&tab[(size_t)j0 * (D_DIM / 4) + lane]);
        const float4 v1 = __ldg(&tab[(size_t)j1 * (D_DIM / 4) + lane]);
        const float4 v2 = __ldg(&tab[(size_t)j2 * (D_DIM / 4) + lane]);
        const float4 v3 = __ldg(&tab[(size_t)j3 * (D_DIM / 4) + lane]);
        a0.x += v0.x; a0.y += v0.y; a0.z += v0.z; a0.w += v0.w;
        a1.x += v1.x; a1.y += v1.y; a1.z += v1.z; a1.w += v1.w;
        a2.x += v2.x; a2.y += v2.y; a2.z += v2.z; a2.w += v2.w;
        a3.x += v3.x; a3.y += v3.y; a3.z += v3.z; a3.w += v3.w;
    }
    for (; l < len; ++l) {
        const int j0 = getidx(l);
        const float4 v0 = __ldg(&tab[(size_t)j0 * (D_DIM / 4) + lane]);
        a0.x += v0.x; a0.y += v0.y; a0.z += v0.z; a0.w += v0.w;
    }

    float4 r;
    r.x = (a0.x + a1.x) + (a2.x + a3.x);
    r.y = (a0.y + a1.y) + (a2.y + a3.y);
    r.z = (a0.z + a1.z) + (a2.z + a3.z);
    r.w = (a0.w + a1.w) + (a2.w + a3.w);
    *(float4*)&g_pooled[(size_t)g * D_DIM + lane * 4] = r;
}

// ---------------------------------------------------------------------------
// Kernel 2: out[32768,128] = pooled @ Wc + bc
// 256 blocks x 256 threads; 128-row tile; K chunked by 32; 8x8 reg tile.
// ---------------------------------------------------------------------------
__global__ __launch_bounds__(256, 2)
void gemm_kernel(float* __restrict__ out) {
    __shared__ float As[128][36];     // row stride 36 floats (144B, 16B aligned)
    __shared__ float Ws[32][128];
    __shared__ float bc_sh[128];

    const int tid = threadIdx.x;
    const int tx = tid & 15;          // col group
    const int ty = tid >> 4;          // row group
    const size_t row0 = (size_t)blockIdx.x * 128;

    if (tid < 128) bc_sh[tid] = g_bc[tid];

    float acc[8][8];
#pragma unroll
    for (int i = 0; i < 8; ++i)
#pragma unroll
        for (int j = 0; j < 8; ++j) acc[i][j] = 0.f;

    for (int kc = 0; kc < D_DIM; kc += 32) {
        // stage A chunk: 128 rows x 32 k (1024 float4, 4 per thread)
#pragma unroll
        for (int u = 0; u < 4; ++u) {
            const int id = tid + u * 256;
            const int r = id >> 3;
            const int q = id & 7;
            const float4 v =
                *(const float4*)&g_pooled[(row0 + r) * D_DIM + kc + q * 4];
            *(float4*)&As[r][q * 4] = v;
        }
        // stage W chunk: 32 k x 128 cols
#pragma unroll
        for (int u = 0; u < 4; ++u) {
            const int id = tid + u * 256;
            const int k = id >> 5;
            const int c = id & 31;
            *(float4*)&Ws[k][c * 4] =
                *(const float4*)&g_Wc[(size_t)(kc + k) * D_DIM + c * 4];
        }
        __syncthreads();

#pragma unroll 8
        for (int k = 0; k < 32; ++k) {
            float a[8];
#pragma unroll
            for (int i = 0; i < 4; ++i) {
                a[i]     = As[ty * 4 + i][k];          // broadcast loads
                a[4 + i] = As[64 + ty * 4 + i][k];
            }
            const float4 w0 = *(const float4*)&Ws[k][tx * 4];        // 256B/16 lanes
            const float4 w1 = *(const float4*)&Ws[k][64 + tx * 4];
            const float w[8] = {w0.x, w0.y, w0.z, w0.w, w1.x, w1.y, w1.z, w1.w};
#pragma unroll
            for (int i = 0; i < 8; ++i)
#pragma unroll
                for (int j = 0; j < 8; ++j) acc[i][j] += a[i] * w[j];
        }
        __syncthreads();
    }

    // epilogue: bias + coalesced float4 stores
#pragma unroll
    for (int i = 0; i < 8; ++i) {
        const int r = (i < 4) ? (ty * 4 + i) : (64 + ty * 4 + (i - 4));
        float* o = out + (row0 + r) * D_DIM;
        float4 v0, v1;
        v0.x = acc[i][0] + bc_sh[tx * 4 + 0];
        v0.y = acc[i][1] + bc_sh[tx * 4 + 1];
        v0.z = acc[i][2] + bc_sh[tx * 4 + 2];
        v0.w = acc[i][3] + bc_sh[tx * 4 + 3];
        v1.x = acc[i][4] + bc_sh[64 + tx * 4 + 0];
        v1.y = acc[i][5] + bc_sh[64 + tx * 4 + 1];
        v1.z = acc[i][6] + bc_sh[64 + tx * 4 + 2];
        v1.w = acc[i][7] + bc_sh[64 + tx * 4 + 3];
        *(float4*)&o[tx * 4] = v0;
        *(float4*)&o[64 + tx * 4] = v1;
    }
}

// ---------------------------------------------------------------------------
extern "C" void kernel_launch(void* const* d_in, const int* in_sizes, int n_in,
                              void* d_out, int out_size) {
    const int*   indices = (const int*)d_in[0];
    const int*   lengths = (const int*)d_in[1];
    const float* tables  = (const float*)d_in[2];
    const float* W1      = (const float*)d_in[3];
    const float* b1      = (const float*)d_in[4];
    const float* W2      = (const float*)d_in[5];
    const float* b2      = (const float*)d_in[6];
    const float* W3      = (const float*)d_in[7];
    const float* b3      = (const float*)d_in[8];
    float* out = (float*)d_out;

    // one warp per row -> 32768 warps -> 4096 blocks of 256
    gather_kernel<<<ROWS_TOTAL / 8, 256>>>(indices, lengths, tables,
                                           W1, b1, W2, b2, W3, b3);
    gemm_kernel<<<ROWS_TOTAL / 128, 256>>>(out);
}